// round 13
// baseline (speedup 1.0000x reference)
#include <cuda_runtime.h>
#include <cuda_fp16.h>
#include <cstdint>

#define NTOK 8192
#define DIM  1024

// ---------------- scratch (allocation-free rule: device globals) -----------
__device__ __half g_fth[(size_t)NTOK * DIM];      // feat as fp16
__device__ __half g_q  [(size_t)NTOK * DIM];      // q fp16
__device__ __half g_k  [(size_t)NTOK * DIM];      // k fp16
__device__ __half g_vt [(size_t)NTOK * DIM];      // v^T fp16: [DIM, NTOK]
__device__ float  g_s  [(size_t)NTOK * NTOK];     // scores fp32
__device__ __half g_p  [(size_t)NTOK * NTOK];     // P*256 fp16
__device__ __half g_wth[(size_t)3 * DIM * DIM];   // concat W^T fp16
__device__ float  g_b3 [3 * DIM];                 // concat bias fp32

#define P_SCALE     256.0f
#define INV_P_SCALE (1.0f / 256.0f)

// ---------------- helpers --------------------------------------------------
__device__ __forceinline__ uint32_t smem_u32(const void* p) {
    uint32_t a;
    asm("{ .reg .u64 t; cvta.to.shared.u64 t, %1; cvt.u32.u64 %0, t; }" : "=r"(a) : "l"(p));
    return a;
}

#define LDSM_X4(r, addr)                                                       \
    asm volatile("ldmatrix.sync.aligned.m8n8.x4.shared.b16 {%0,%1,%2,%3}, [%4];" \
        : "=r"((r)[0]), "=r"((r)[1]), "=r"((r)[2]), "=r"((r)[3]) : "r"(addr))

__device__ __forceinline__ void mma_f16(float c[4], const uint32_t a[4],
                                        uint32_t b0, uint32_t b1) {
    asm volatile(
        "mma.sync.aligned.m16n8k16.row.col.f32.f16.f16.f32 "
        "{%0,%1,%2,%3}, {%4,%5,%6,%7}, {%8,%9}, {%0,%1,%2,%3};"
        : "+f"(c[0]), "+f"(c[1]), "+f"(c[2]), "+f"(c[3])
        : "r"(a[0]), "r"(a[1]), "r"(a[2]), "r"(a[3]),
          "r"(b0), "r"(b1));
}

// ---------------- stage loader ---------------------------------------------
// Stage: 256 rows x 128B (64 fp16). Rows [0,128) = A rows (m), [128,256) = B
// rows (n). Row r, 16B chunk c at r*128 + ((c ^ (r&7))*16)  (XOR swizzle).
// 128 threads -> 16 iterations. K in fp16 elements; BK = 64.
__device__ __forceinline__ void load_stage(uint32_t sbase,
                                           const __half* __restrict__ A,
                                           const __half* __restrict__ B,
                                           int bm, int bn, int K, int kt, int tid)
{
    #pragma unroll
    for (int it = 0; it < 16; it++) {
        int idx = it * 128 + tid;          // 0..2047
        int row = idx >> 3;                // 0..255
        int ch  = idx & 7;                 // 0..7
        const __half* g = (row < 128)
            ? (A + (size_t)(bm + row) * K)
            : (B + (size_t)(bn + row - 128) * K);
        g += kt * 64 + ch * 8;
        uint32_t dst = sbase + (uint32_t)(row * 128) + (uint32_t)((ch ^ (row & 7)) << 4);
        asm volatile("cp.async.cg.shared.global [%0], [%1], 16;" :: "r"(dst), "l"(g) : "memory");
    }
}

// ---------------------------------------------------------------------------
// FP16 HMMA NT GEMM: C[M,N] = A[M,K] @ B[N,K]^T  (fp32 accumulate)
// CTA tile 128x128, 128 thr (4 warps of 64x64, 2m x 2n), BK=64 (4 k16 steps),
// 3-stage cp.async pipeline (prefetch AFTER compute — L1tex queue priority),
// 2 CTAs/SM, ldmatrix fragments double-buffered across k-steps.
// MODE 0: C fp32, *scale if SCALE, +bias[col] if BIAS.
// MODE 1: fused-QKV routing, fp16 outputs — cols [0,1024)->g_q,
//         [1024,2048)->g_k, [2048,3072)->g_vt transposed; bias=g_b3.
// ---------------------------------------------------------------------------
template <int MODE, bool BIAS, bool SCALE>
__global__ void __launch_bounds__(128, 2)
gemm_tc(const __half* __restrict__ A, const __half* __restrict__ B,
        float* __restrict__ C, int K, int ldc, float scale)
{
    constexpr int STAGE = 32768;           // 256 * 128 bytes
    extern __shared__ char dsm[];
    const uint32_t smbase = (smem_u32(dsm) + 127u) & ~127u;

    const int tid  = threadIdx.x;
    const int wid  = tid >> 5;
    const int lane = tid & 31;
    const int g    = lane >> 2;            // 0..7
    const int tig  = lane & 3;             // 0..3
    const int lr   = lane & 7;             // ldsm row within 8x8 matrix
    const int quad = lane >> 3;            // ldsm matrix id 0..3
    const int wm   = (wid & 1) * 64;
    const int wn   = (wid >> 1) * 64;

    const int bm = blockIdx.y * 128;
    const int bn = blockIdx.x * 128;

    // ldsm per-lane row byte-offsets (stage-relative)
    // Both A and B use: (quad&1)->+8 rows, (quad>>1)->k-chunk+1.
    const int hi = quad >> 1;              // k-chunk +1 for matrices 2,3
    uint32_t a_row[4], b_row[4];
    #pragma unroll
    for (int im = 0; im < 4; im++)
        a_row[im] = (uint32_t)((wm + im * 16 + ((quad & 1) << 3) + lr) * 128);
    #pragma unroll
    for (int p = 0; p < 4; p++)
        b_row[p] = (uint32_t)((128 + wn + p * 16 + ((quad & 1) << 3) + lr) * 128);

    float c[4][8][4];
    #pragma unroll
    for (int im = 0; im < 4; im++)
        #pragma unroll
        for (int in = 0; in < 8; in++)
            #pragma unroll
            for (int r = 0; r < 4; r++) c[im][in][r] = 0.0f;

    const int KT = K / 64;

    load_stage(smbase + 0 * STAGE, A, B, bm, bn, K, 0, tid);
    asm volatile("cp.async.commit_group;" ::: "memory");
    load_stage(smbase + 1 * STAGE, A, B, bm, bn, K, 1, tid);
    asm volatile("cp.async.commit_group;" ::: "memory");

    uint32_t a[2][4][4], b[2][4][4];

    for (int kt = 0; kt < KT; kt++) {
        asm volatile("cp.async.wait_group 1;" ::: "memory");
        __syncthreads();   // stage kt%3 visible; prior readers of reused stage done

        const uint32_t sb = smbase + (kt % 3) * STAGE;

        // preload k-step 0 fragments into buffer 0
        {
            const uint32_t so = (uint32_t)((hi ^ lr) << 4);
            #pragma unroll
            for (int im = 0; im < 4; im++) LDSM_X4(a[0][im], sb + a_row[im] + so);
            #pragma unroll
            for (int p = 0; p < 4; p++)   LDSM_X4(b[0][p],  sb + b_row[p]  + so);
        }

        #pragma unroll
        for (int ks = 0; ks < 4; ks++) {
            const int cur = ks & 1;
            if (ks < 3) {
                const int nxt = cur ^ 1;
                const uint32_t so = (uint32_t)(((2 * (ks + 1) + hi) ^ lr) << 4);
                #pragma unroll
                for (int im = 0; im < 4; im++) LDSM_X4(a[nxt][im], sb + a_row[im] + so);
                #pragma unroll
                for (int p = 0; p < 4; p++)   LDSM_X4(b[nxt][p],  sb + b_row[p]  + so);
            }
            // b-frag for n-group 2p   = {r0, r2} (rows +0, k-chunks 0/1)
            // b-frag for n-group 2p+1 = {r1, r3} (rows +8)
            #pragma unroll
            for (int im = 0; im < 4; im++)
                #pragma unroll
                for (int p = 0; p < 4; p++) {
                    mma_f16(c[im][2 * p],     a[cur][im], b[cur][p][0], b[cur][p][2]);
                    mma_f16(c[im][2 * p + 1], a[cur][im], b[cur][p][1], b[cur][p][3]);
                }
        }

        // prefetch AFTER compute: keeps LDSM ahead of cp.async in L1tex queue
        if (kt + 2 < KT)
            load_stage(smbase + ((kt + 2) % 3) * STAGE, A, B, bm, bn, K, kt + 2, tid);
        asm volatile("cp.async.commit_group;" ::: "memory");
    }

    // ---- epilogue ----  (col = bn + wn + in*8 + tig*2, row = bm + wm + im*16 + g)
    #pragma unroll
    for (int im = 0; im < 4; im++) {
        #pragma unroll
        for (int in = 0; in < 8; in++) {
            const int row = bm + wm + im * 16 + g;
            const int col = bn + wn + in * 8 + tig * 2;
            float v0 = c[im][in][0], v1 = c[im][in][1];
            float v2 = c[im][in][2], v3 = c[im][in][3];
            if (MODE == 1) {
                float2 b2 = *(const float2*)&g_b3[col];
                v0 += b2.x; v1 += b2.y; v2 += b2.x; v3 += b2.y;
                if (col < DIM) {
                    *(__half2*)&g_q[(size_t)row       * DIM + col] = __floats2half2_rn(v0, v1);
                    *(__half2*)&g_q[(size_t)(row + 8) * DIM + col] = __floats2half2_rn(v2, v3);
                } else if (col < 2 * DIM) {
                    const int cc = col - DIM;
                    *(__half2*)&g_k[(size_t)row       * DIM + cc] = __floats2half2_rn(v0, v1);
                    *(__half2*)&g_k[(size_t)(row + 8) * DIM + cc] = __floats2half2_rn(v2, v3);
                } else {
                    const int cc = col - 2 * DIM;
                    g_vt[(size_t)cc       * NTOK + row    ] = __float2half_rn(v0);
                    g_vt[(size_t)(cc + 1) * NTOK + row    ] = __float2half_rn(v1);
                    g_vt[(size_t)cc       * NTOK + row + 8] = __float2half_rn(v2);
                    g_vt[(size_t)(cc + 1) * NTOK + row + 8] = __float2half_rn(v3);
                }
            } else {
                if (SCALE) { v0 *= scale; v1 *= scale; v2 *= scale; v3 *= scale; }
                *(float2*)&C[(size_t)row       * ldc + col] = make_float2(v0, v1);
                *(float2*)&C[(size_t)(row + 8) * ldc + col] = make_float2(v2, v3);
            }
        }
    }
}

// ---------------------------------------------------------------------------
// bias concat (own tiny launch — also shifts the ncu capture slot onto a GEMM)
// ---------------------------------------------------------------------------
__global__ void bias_concat_kernel(const float* __restrict__ bq,
                                   const float* __restrict__ bk,
                                   const float* __restrict__ bv)
{
    int i = blockIdx.x * blockDim.x + threadIdx.x;
    if (i < DIM)            g_b3[i] = bq[i];
    else if (i < 2 * DIM)   g_b3[i] = bk[i - DIM];
    else if (i < 3 * DIM)   g_b3[i] = bv[i - 2 * DIM];
}

// ---------------------------------------------------------------------------
// prep: z=0..2 -> transpose W_z to fp16 into g_wth slab z;
//       z=3    -> feat -> fp16 (g_fth).
// grid (32, 32, 4), block (32, 8).
// ---------------------------------------------------------------------------
__global__ void prep_kernel(const float* __restrict__ feat,
                            const float* __restrict__ Wq,
                            const float* __restrict__ Wk,
                            const float* __restrict__ Wv)
{
    const int z = blockIdx.z;
    if (z < 3) {
        const float* in = (z == 0) ? Wq : (z == 1) ? Wk : Wv;
        __half* out = g_wth + (size_t)z * DIM * DIM;
        __shared__ float t[32][33];
        int bx = blockIdx.x * 32, by = blockIdx.y * 32;
        #pragma unroll
        for (int j = 0; j < 32; j += 8)
            t[threadIdx.y + j][threadIdx.x] =
                in[(size_t)(by + threadIdx.y + j) * DIM + bx + threadIdx.x];
        __syncthreads();
        #pragma unroll
        for (int j = 0; j < 32; j += 8)
            out[(size_t)(bx + threadIdx.y + j) * DIM + by + threadIdx.x] =
                __float2half_rn(t[threadIdx.x][threadIdx.y + j]);
    } else {
        const int bid = blockIdx.y * 32 + blockIdx.x;     // 0..1023
        const int tid = threadIdx.y * 32 + threadIdx.x;   // 0..255
        const float4* fin = (const float4*)feat;
        __half2* fout = (__half2*)g_fth;
        size_t base = (size_t)bid * 2048;
        #pragma unroll
        for (int i = 0; i < 8; i++) {
            size_t idx = base + i * 256 + tid;
            float4 v = fin[idx];
            fout[2 * idx]     = __floats2half2_rn(v.x, v.y);
            fout[2 * idx + 1] = __floats2half2_rn(v.z, v.w);
        }
    }
}

// ---------------------------------------------------------------------------
// Row softmax: read fp32 scores, write fp16 P*256. 256 threads REQUIRED.
// ---------------------------------------------------------------------------
__global__ void softmax_kernel(const float* __restrict__ S, __half* __restrict__ P)
{
    const int row = blockIdx.x;
    const int tid = threadIdx.x;
    const float4* p = (const float4*)(S + (size_t)row * NTOK);
    __half2* po = (__half2*)(P + (size_t)row * NTOK);

    float4 v[8];
    float m = -1e30f;
    #pragma unroll
    for (int i = 0; i < 8; i++) {
        v[i] = p[tid + i * 256];
        m = fmaxf(m, fmaxf(fmaxf(v[i].x, v[i].y), fmaxf(v[i].z, v[i].w)));
    }
    #pragma unroll
    for (int o = 16; o; o >>= 1) m = fmaxf(m, __shfl_xor_sync(0xffffffffu, m, o));

    __shared__ float red[8];
    if ((tid & 31) == 0) red[tid >> 5] = m;
    __syncthreads();
    m = red[0];
    #pragma unroll
    for (int i = 1; i < 8; i++) m = fmaxf(m, red[i]);
    __syncthreads();

    float s = 0.0f;
    #pragma unroll
    for (int i = 0; i < 8; i++) {
        v[i].x = __expf(v[i].x - m);
        v[i].y = __expf(v[i].y - m);
        v[i].z = __expf(v[i].z - m);
        v[i].w = __expf(v[i].w - m);
        s += (v[i].x + v[i].y) + (v[i].z + v[i].w);
    }
    #pragma unroll
    for (int o = 16; o; o >>= 1) s += __shfl_xor_sync(0xffffffffu, s, o);
    if ((tid & 31) == 0) red[tid >> 5] = s;
    __syncthreads();
    s = 0.0f;
    #pragma unroll
    for (int i = 0; i < 8; i++) s += red[i];

    const float inv = P_SCALE / s;
    #pragma unroll
    for (int i = 0; i < 8; i++) {
        const int j = tid + i * 256;
        po[2 * j]     = __floats2half2_rn(v[i].x * inv, v[i].y * inv);
        po[2 * j + 1] = __floats2half2_rn(v[i].z * inv, v[i].w * inv);
    }
}

// ---------------------------------------------------------------------------
extern "C" void kernel_launch(void* const* d_in, const int* in_sizes, int n_in,
                              void* d_out, int out_size)
{
    const float* feat = (const float*)d_in[0];
    const float* Wq   = (const float*)d_in[1];
    const float* bq   = (const float*)d_in[2];
    const float* Wk   = (const float*)d_in[3];
    const float* bk   = (const float*)d_in[4];
    const float* Wv   = (const float*)d_in[5];
    const float* bv   = (const float*)d_in[6];
    float* out = (float*)d_out;

    __half *fth, *q, *k, *vt, *p, *wth;
    float *s;
    cudaGetSymbolAddress((void**)&fth, g_fth);
    cudaGetSymbolAddress((void**)&q,   g_q);
    cudaGetSymbolAddress((void**)&k,   g_k);
    cudaGetSymbolAddress((void**)&vt,  g_vt);
    cudaGetSymbolAddress((void**)&s,   g_s);
    cudaGetSymbolAddress((void**)&p,   g_p);
    cudaGetSymbolAddress((void**)&wth, g_wth);

    const int DSM = 3 * 32768 + 128;
    cudaFuncSetAttribute(gemm_tc<1, true,  false>, cudaFuncAttributeMaxDynamicSharedMemorySize, DSM);
    cudaFuncSetAttribute(gemm_tc<0, false, true >, cudaFuncAttributeMaxDynamicSharedMemorySize, DSM);

    dim3 gblk(128);                        // GEMM blocks (128 threads)
    dim3 gqkv(3 * DIM / 128, NTOK / 128);  // (24, 64)
    dim3 gsc(NTOK / 128, NTOK / 128);      // (64, 64)
    dim3 gpv(DIM / 128, NTOK / 128);       // (8, 64)

    // launch 0: bias concat (tiny; also aligns ncu capture slot onto a GEMM)
    bias_concat_kernel<<<12, 256>>>(bq, bk, bv);

    // launch 1: prep (W transposes->fp16, feat->fp16)
    prep_kernel<<<dim3(32, 32, 4), dim3(32, 8)>>>(feat, Wq, Wk, Wv);

    // launch 2: fused QKV: [q | k | vt] = fth @ Wcat^T + bcat  (fp16 outputs)
    gemm_tc<1, true, false><<<gqkv, gblk, DSM>>>(fth, wth, nullptr, DIM, 0, 1.0f);

    // launch 3: scores = (q @ k^T) / 32   (fp32 output)
    gemm_tc<0, false, true><<<gsc, gblk, DSM>>>(q, k, s, DIM, NTOK, 0.03125f);

    // launch 4: softmax rows: fp32 scores -> fp16 P*256 — 256 threads REQUIRED
    softmax_kernel<<<NTOK, 256>>>(s, p);

    // launch 5: out = (P*256 @ vt^T) / 256   (fp32 output)
    gemm_tc<0, false, true><<<gpv, gblk, DSM>>>(p, vt, out, NTOK, DIM, INV_P_SCALE);
}

// round 14
// speedup vs baseline: 1.4476x; 1.4476x over previous
#include <cuda_runtime.h>
#include <cuda_fp16.h>
#include <cstdint>

#define NTOK 8192
#define DIM  1024

// ---------------- scratch (allocation-free rule: device globals) -----------
__device__ __half g_fth[(size_t)NTOK * DIM];      // feat as fp16
__device__ __half g_q  [(size_t)NTOK * DIM];      // q fp16
__device__ __half g_k  [(size_t)NTOK * DIM];      // k fp16
__device__ __half g_vt [(size_t)NTOK * DIM];      // v^T fp16: [DIM, NTOK]
__device__ float  g_s  [(size_t)NTOK * NTOK];     // scores fp32
__device__ __half g_p  [(size_t)NTOK * NTOK];     // P*256 fp16
__device__ __half g_wth[(size_t)3 * DIM * DIM];   // concat W^T fp16
__device__ float  g_b3 [3 * DIM];                 // concat bias fp32

#define P_SCALE     256.0f
#define INV_P_SCALE (1.0f / 256.0f)

// ---------------- helpers --------------------------------------------------
__device__ __forceinline__ uint32_t smem_u32(const void* p) {
    uint32_t a;
    asm("{ .reg .u64 t; cvta.to.shared.u64 t, %1; cvt.u32.u64 %0, t; }" : "=r"(a) : "l"(p));
    return a;
}

#define LDSM_X4(r, addr)                                                       \
    asm volatile("ldmatrix.sync.aligned.m8n8.x4.shared.b16 {%0,%1,%2,%3}, [%4];" \
        : "=r"((r)[0]), "=r"((r)[1]), "=r"((r)[2]), "=r"((r)[3]) : "r"(addr))

__device__ __forceinline__ void mma_f16(float c[4], const uint32_t a[4],
                                        uint32_t b0, uint32_t b1) {
    asm volatile(
        "mma.sync.aligned.m16n8k16.row.col.f32.f16.f16.f32 "
        "{%0,%1,%2,%3}, {%4,%5,%6,%7}, {%8,%9}, {%0,%1,%2,%3};"
        : "+f"(c[0]), "+f"(c[1]), "+f"(c[2]), "+f"(c[3])
        : "r"(a[0]), "r"(a[1]), "r"(a[2]), "r"(a[3]),
          "r"(b0), "r"(b1));
}

// ---------------- stage loader ---------------------------------------------
// Stage: 256 rows x 128B (64 fp16). Rows [0,128) = A rows (m), [128,256) = B
// rows (n). Row r, 16B chunk c at r*128 + ((c ^ (r&7))*16)  (XOR swizzle).
// 256 threads -> 8 iterations. K in fp16 elements; BK = 64.
__device__ __forceinline__ void load_stage(uint32_t sbase,
                                           const __half* __restrict__ A,
                                           const __half* __restrict__ B,
                                           int bm, int bn, int K, int kt, int tid)
{
    #pragma unroll
    for (int it = 0; it < 8; it++) {
        int idx = it * 256 + tid;          // 0..2047
        int row = idx >> 3;                // 0..255
        int ch  = idx & 7;                 // 0..7
        const __half* g = (row < 128)
            ? (A + (size_t)(bm + row) * K)
            : (B + (size_t)(bn + row - 128) * K);
        g += kt * 64 + ch * 8;
        uint32_t dst = sbase + (uint32_t)(row * 128) + (uint32_t)((ch ^ (row & 7)) << 4);
        asm volatile("cp.async.cg.shared.global [%0], [%1], 16;" :: "r"(dst), "l"(g) : "memory");
    }
}

// ---------------------------------------------------------------------------
// FP16 HMMA NT GEMM: C[M,N] = A[M,K] @ B[N,K]^T  (fp32 accumulate)
// CTA tile 128x128, 256 thr (8 warps of 64x32, 2m x 4n), BK=64 (4 k16 steps),
// 3-stage cp.async pipeline (prefetch AFTER compute — L1tex queue priority),
// 2 CTAs/SM (16 warps/SM = 4/SMSP for latency hiding), single-buffered
// ldmatrix fragments (register diet: fit 128 regs/thread).
// MODE 0: C fp32, *scale if SCALE, +bias[col] if BIAS.
// MODE 1: fused-QKV routing, fp16 outputs — cols [0,1024)->g_q,
//         [1024,2048)->g_k, [2048,3072)->g_vt transposed; bias=g_b3.
// ---------------------------------------------------------------------------
template <int MODE, bool BIAS, bool SCALE>
__global__ void __launch_bounds__(256, 2)
gemm_tc(const __half* __restrict__ A, const __half* __restrict__ B,
        float* __restrict__ C, int K, int ldc, float scale)
{
    constexpr int STAGE = 32768;           // 256 * 128 bytes
    extern __shared__ char dsm[];
    const uint32_t smbase = (smem_u32(dsm) + 127u) & ~127u;

    const int tid  = threadIdx.x;
    const int wid  = tid >> 5;
    const int lane = tid & 31;
    const int g    = lane >> 2;            // 0..7
    const int tig  = lane & 3;             // 0..3
    const int lr   = lane & 7;             // ldsm row within 8x8 matrix
    const int quad = lane >> 3;            // ldsm matrix id 0..3
    const int wm   = (wid & 1) * 64;       // 2 m-warps
    const int wn   = (wid >> 1) * 32;      // 4 n-warps

    const int bm = blockIdx.y * 128;
    const int bn = blockIdx.x * 128;

    // ldsm per-lane row byte-offsets (stage-relative)
    // Both A and B: (quad&1)->+8 rows, (quad>>1)->k-chunk+1.
    const int hi = quad >> 1;
    uint32_t a_row[4], b_row[2];
    #pragma unroll
    for (int im = 0; im < 4; im++)
        a_row[im] = (uint32_t)((wm + im * 16 + ((quad & 1) << 3) + lr) * 128);
    #pragma unroll
    for (int p = 0; p < 2; p++)
        b_row[p] = (uint32_t)((128 + wn + p * 16 + ((quad & 1) << 3) + lr) * 128);

    // k-step swizzle offsets (kt-invariant)
    uint32_t so_tab[4];
    #pragma unroll
    for (int ks = 0; ks < 4; ks++)
        so_tab[ks] = (uint32_t)(((2 * ks + hi) ^ lr) << 4);

    float c[4][4][4];
    #pragma unroll
    for (int im = 0; im < 4; im++)
        #pragma unroll
        for (int in = 0; in < 4; in++)
            #pragma unroll
            for (int r = 0; r < 4; r++) c[im][in][r] = 0.0f;

    const int KT = K / 64;

    load_stage(smbase + 0 * STAGE, A, B, bm, bn, K, 0, tid);
    asm volatile("cp.async.commit_group;" ::: "memory");
    load_stage(smbase + 1 * STAGE, A, B, bm, bn, K, 1, tid);
    asm volatile("cp.async.commit_group;" ::: "memory");

    for (int kt = 0; kt < KT; kt++) {
        asm volatile("cp.async.wait_group 1;" ::: "memory");
        __syncthreads();   // stage kt%3 visible; prior readers of reused stage done

        const uint32_t sb = smbase + (kt % 3) * STAGE;

        #pragma unroll
        for (int ks = 0; ks < 4; ks++) {
            const uint32_t so = so_tab[ks];
            uint32_t a[4][4], b[2][4];
            #pragma unroll
            for (int im = 0; im < 4; im++) LDSM_X4(a[im], sb + a_row[im] + so);
            #pragma unroll
            for (int p = 0; p < 2; p++)   LDSM_X4(b[p],  sb + b_row[p]  + so);

            // b-frag n-group 2p   = {r0, r2}; n-group 2p+1 = {r1, r3}
            #pragma unroll
            for (int im = 0; im < 4; im++)
                #pragma unroll
                for (int p = 0; p < 2; p++) {
                    mma_f16(c[im][2 * p],     a[im], b[p][0], b[p][2]);
                    mma_f16(c[im][2 * p + 1], a[im], b[p][1], b[p][3]);
                }
        }

        // prefetch AFTER compute: keeps LDSM ahead of cp.async in L1tex queue
        if (kt + 2 < KT)
            load_stage(smbase + ((kt + 2) % 3) * STAGE, A, B, bm, bn, K, kt + 2, tid);
        asm volatile("cp.async.commit_group;" ::: "memory");
    }

    // ---- epilogue ----  (col = bn + wn + in*8 + tig*2, row = bm + wm + im*16 + g)
    #pragma unroll
    for (int im = 0; im < 4; im++) {
        #pragma unroll
        for (int in = 0; in < 4; in++) {
            const int row = bm + wm + im * 16 + g;
            const int col = bn + wn + in * 8 + tig * 2;
            float v0 = c[im][in][0], v1 = c[im][in][1];
            float v2 = c[im][in][2], v3 = c[im][in][3];
            if (MODE == 1) {
                float2 b2 = *(const float2*)&g_b3[col];
                v0 += b2.x; v1 += b2.y; v2 += b2.x; v3 += b2.y;
                if (col < DIM) {
                    *(__half2*)&g_q[(size_t)row       * DIM + col] = __floats2half2_rn(v0, v1);
                    *(__half2*)&g_q[(size_t)(row + 8) * DIM + col] = __floats2half2_rn(v2, v3);
                } else if (col < 2 * DIM) {
                    const int cc = col - DIM;
                    *(__half2*)&g_k[(size_t)row       * DIM + cc] = __floats2half2_rn(v0, v1);
                    *(__half2*)&g_k[(size_t)(row + 8) * DIM + cc] = __floats2half2_rn(v2, v3);
                } else {
                    const int cc = col - 2 * DIM;
                    g_vt[(size_t)cc       * NTOK + row    ] = __float2half_rn(v0);
                    g_vt[(size_t)(cc + 1) * NTOK + row    ] = __float2half_rn(v1);
                    g_vt[(size_t)cc       * NTOK + row + 8] = __float2half_rn(v2);
                    g_vt[(size_t)(cc + 1) * NTOK + row + 8] = __float2half_rn(v3);
                }
            } else {
                if (SCALE) { v0 *= scale; v1 *= scale; v2 *= scale; v3 *= scale; }
                *(float2*)&C[(size_t)row       * ldc + col] = make_float2(v0, v1);
                *(float2*)&C[(size_t)(row + 8) * ldc + col] = make_float2(v2, v3);
            }
        }
    }
}

// ---------------------------------------------------------------------------
// bias concat (own tiny launch)
// ---------------------------------------------------------------------------
__global__ void bias_concat_kernel(const float* __restrict__ bq,
                                   const float* __restrict__ bk,
                                   const float* __restrict__ bv)
{
    int i = blockIdx.x * blockDim.x + threadIdx.x;
    if (i < DIM)            g_b3[i] = bq[i];
    else if (i < 2 * DIM)   g_b3[i] = bk[i - DIM];
    else if (i < 3 * DIM)   g_b3[i] = bv[i - 2 * DIM];
}

// ---------------------------------------------------------------------------
// prep: z=0..2 -> transpose W_z to fp16 into g_wth slab z;
//       z=3    -> feat -> fp16 (g_fth).
// grid (32, 32, 4), block (32, 8).
// ---------------------------------------------------------------------------
__global__ void prep_kernel(const float* __restrict__ feat,
                            const float* __restrict__ Wq,
                            const float* __restrict__ Wk,
                            const float* __restrict__ Wv)
{
    const int z = blockIdx.z;
    if (z < 3) {
        const float* in = (z == 0) ? Wq : (z == 1) ? Wk : Wv;
        __half* out = g_wth + (size_t)z * DIM * DIM;
        __shared__ float t[32][33];
        int bx = blockIdx.x * 32, by = blockIdx.y * 32;
        #pragma unroll
        for (int j = 0; j < 32; j += 8)
            t[threadIdx.y + j][threadIdx.x] =
                in[(size_t)(by + threadIdx.y + j) * DIM + bx + threadIdx.x];
        __syncthreads();
        #pragma unroll
        for (int j = 0; j < 32; j += 8)
            out[(size_t)(bx + threadIdx.y + j) * DIM + by + threadIdx.x] =
                __float2half_rn(t[threadIdx.x][threadIdx.y + j]);
    } else {
        const int bid = blockIdx.y * 32 + blockIdx.x;     // 0..1023
        const int tid = threadIdx.y * 32 + threadIdx.x;   // 0..255
        const float4* fin = (const float4*)feat;
        __half2* fout = (__half2*)g_fth;
        size_t base = (size_t)bid * 2048;
        #pragma unroll
        for (int i = 0; i < 8; i++) {
            size_t idx = base + i * 256 + tid;
            float4 v = fin[idx];
            fout[2 * idx]     = __floats2half2_rn(v.x, v.y);
            fout[2 * idx + 1] = __floats2half2_rn(v.z, v.w);
        }
    }
}

// ---------------------------------------------------------------------------
// Row softmax: read fp32 scores, write fp16 P*256. 256 threads REQUIRED.
// ---------------------------------------------------------------------------
__global__ void softmax_kernel(const float* __restrict__ S, __half* __restrict__ P)
{
    const int row = blockIdx.x;
    const int tid = threadIdx.x;
    const float4* p = (const float4*)(S + (size_t)row * NTOK);
    __half2* po = (__half2*)(P + (size_t)row * NTOK);

    float4 v[8];
    float m = -1e30f;
    #pragma unroll
    for (int i = 0; i < 8; i++) {
        v[i] = p[tid + i * 256];
        m = fmaxf(m, fmaxf(fmaxf(v[i].x, v[i].y), fmaxf(v[i].z, v[i].w)));
    }
    #pragma unroll
    for (int o = 16; o; o >>= 1) m = fmaxf(m, __shfl_xor_sync(0xffffffffu, m, o));

    __shared__ float red[8];
    if ((tid & 31) == 0) red[tid >> 5] = m;
    __syncthreads();
    m = red[0];
    #pragma unroll
    for (int i = 1; i < 8; i++) m = fmaxf(m, red[i]);
    __syncthreads();

    float s = 0.0f;
    #pragma unroll
    for (int i = 0; i < 8; i++) {
        v[i].x = __expf(v[i].x - m);
        v[i].y = __expf(v[i].y - m);
        v[i].z = __expf(v[i].z - m);
        v[i].w = __expf(v[i].w - m);
        s += (v[i].x + v[i].y) + (v[i].z + v[i].w);
    }
    #pragma unroll
    for (int o = 16; o; o >>= 1) s += __shfl_xor_sync(0xffffffffu, s, o);
    if ((tid & 31) == 0) red[tid >> 5] = s;
    __syncthreads();
    s = 0.0f;
    #pragma unroll
    for (int i = 0; i < 8; i++) s += red[i];

    const float inv = P_SCALE / s;
    #pragma unroll
    for (int i = 0; i < 8; i++) {
        const int j = tid + i * 256;
        po[2 * j]     = __floats2half2_rn(v[i].x * inv, v[i].y * inv);
        po[2 * j + 1] = __floats2half2_rn(v[i].z * inv, v[i].w * inv);
    }
}

// ---------------------------------------------------------------------------
extern "C" void kernel_launch(void* const* d_in, const int* in_sizes, int n_in,
                              void* d_out, int out_size)
{
    const float* feat = (const float*)d_in[0];
    const float* Wq   = (const float*)d_in[1];
    const float* bq   = (const float*)d_in[2];
    const float* Wk   = (const float*)d_in[3];
    const float* bk   = (const float*)d_in[4];
    const float* Wv   = (const float*)d_in[5];
    const float* bv   = (const float*)d_in[6];
    float* out = (float*)d_out;

    __half *fth, *q, *k, *vt, *p, *wth;
    float *s;
    cudaGetSymbolAddress((void**)&fth, g_fth);
    cudaGetSymbolAddress((void**)&q,   g_q);
    cudaGetSymbolAddress((void**)&k,   g_k);
    cudaGetSymbolAddress((void**)&vt,  g_vt);
    cudaGetSymbolAddress((void**)&s,   g_s);
    cudaGetSymbolAddress((void**)&p,   g_p);
    cudaGetSymbolAddress((void**)&wth, g_wth);

    const int DSM = 3 * 32768 + 128;
    cudaFuncSetAttribute(gemm_tc<1, true,  false>, cudaFuncAttributeMaxDynamicSharedMemorySize, DSM);
    cudaFuncSetAttribute(gemm_tc<0, false, true >, cudaFuncAttributeMaxDynamicSharedMemorySize, DSM);

    dim3 gblk(256);                        // GEMM blocks (256 threads)
    dim3 gqkv(3 * DIM / 128, NTOK / 128);  // (24, 64)
    dim3 gsc(NTOK / 128, NTOK / 128);      // (64, 64)
    dim3 gpv(DIM / 128, NTOK / 128);       // (8, 64)

    // launch 0: bias concat
    bias_concat_kernel<<<12, 256>>>(bq, bk, bv);

    // launch 1: prep (W transposes->fp16, feat->fp16)
    prep_kernel<<<dim3(32, 32, 4), dim3(32, 8)>>>(feat, Wq, Wk, Wv);

    // launch 2: fused QKV: [q | k | vt] = fth @ Wcat^T + bcat  (fp16 outputs)
    gemm_tc<1, true, false><<<gqkv, gblk, DSM>>>(fth, wth, nullptr, DIM, 0, 1.0f);

    // launch 3: scores = (q @ k^T) / 32   (fp32 output)
    gemm_tc<0, false, true><<<gsc, gblk, DSM>>>(q, k, s, DIM, NTOK, 0.03125f);

    // launch 4: softmax rows: fp32 scores -> fp16 P*256 — 256 threads REQUIRED
    softmax_kernel<<<NTOK, 256>>>(s, p);

    // launch 5: out = (P*256 @ vt^T) / 256   (fp32 output)
    gemm_tc<0, false, true><<<gpv, gblk, DSM>>>(p, vt, out, NTOK, DIM, INV_P_SCALE);
}

// round 15
// speedup vs baseline: 1.4898x; 1.0292x over previous
#include <cuda_runtime.h>
#include <cuda_fp16.h>
#include <cstdint>

#define NTOK 8192
#define DIM  1024

// ---------------- scratch (allocation-free rule: device globals) -----------
__device__ __half g_fth[(size_t)NTOK * DIM];      // feat as fp16
__device__ __half g_q  [(size_t)NTOK * DIM];      // q fp16
__device__ __half g_k  [(size_t)NTOK * DIM];      // k fp16
__device__ __half g_vt [(size_t)NTOK * DIM];      // v^T fp16: [DIM, NTOK]
__device__ __half g_e  [(size_t)NTOK * NTOK];     // E = exp(s)*2^-6, fp16
__device__ float  g_rinv[NTOK];                   // 1 / rowsum(E)
__device__ __half g_wth[(size_t)3 * DIM * DIM];   // concat W^T fp16
__device__ float  g_b3 [3 * DIM];                 // concat bias fp32

#define E_SCALE 0.015625f                          // 2^-6 overflow guard

// ---------------- helpers --------------------------------------------------
__device__ __forceinline__ uint32_t smem_u32(const void* p) {
    uint32_t a;
    asm("{ .reg .u64 t; cvta.to.shared.u64 t, %1; cvt.u32.u64 %0, t; }" : "=r"(a) : "l"(p));
    return a;
}

#define LDSM_X4(r, addr)                                                       \
    asm volatile("ldmatrix.sync.aligned.m8n8.x4.shared.b16 {%0,%1,%2,%3}, [%4];" \
        : "=r"((r)[0]), "=r"((r)[1]), "=r"((r)[2]), "=r"((r)[3]) : "r"(addr))

__device__ __forceinline__ void mma_f16(float c[4], const uint32_t a[4],
                                        uint32_t b0, uint32_t b1) {
    asm volatile(
        "mma.sync.aligned.m16n8k16.row.col.f32.f16.f16.f32 "
        "{%0,%1,%2,%3}, {%4,%5,%6,%7}, {%8,%9}, {%0,%1,%2,%3};"
        : "+f"(c[0]), "+f"(c[1]), "+f"(c[2]), "+f"(c[3])
        : "r"(a[0]), "r"(a[1]), "r"(a[2]), "r"(a[3]),
          "r"(b0), "r"(b1));
}

// ---------------- stage loader ---------------------------------------------
// Stage: 256 rows x 128B (64 fp16). Rows [0,128) = A rows (m), [128,256) = B
// rows (n). Row r, 16B chunk c at r*128 + ((c ^ (r&7))*16)  (XOR swizzle).
// 256 threads -> 8 iterations. K in fp16 elements; BK = 64.
__device__ __forceinline__ void load_stage(uint32_t sbase,
                                           const __half* __restrict__ A,
                                           const __half* __restrict__ B,
                                           int bm, int bn, int K, int kt, int tid)
{
    #pragma unroll
    for (int it = 0; it < 8; it++) {
        int idx = it * 256 + tid;          // 0..2047
        int row = idx >> 3;                // 0..255
        int ch  = idx & 7;                 // 0..7
        const __half* g = (row < 128)
            ? (A + (size_t)(bm + row) * K)
            : (B + (size_t)(bn + row - 128) * K);
        g += kt * 64 + ch * 8;
        uint32_t dst = sbase + (uint32_t)(row * 128) + (uint32_t)((ch ^ (row & 7)) << 4);
        asm volatile("cp.async.cg.shared.global [%0], [%1], 16;" :: "r"(dst), "l"(g) : "memory");
    }
}

// ---------------------------------------------------------------------------
// FP16 HMMA NT GEMM: C[M,N] = A[M,K] @ B[N,K]^T  (fp32 accumulate)
// CTA tile 128x128, 256 thr (8 warps of 64x32, 2m x 4n), BK=64 (4 k16 steps),
// 3-stage cp.async pipeline (prefetch AFTER compute — L1tex queue priority),
// 2 CTAs/SM (16 warps/SM = 4/SMSP), single-buffered ldmatrix fragments.
// MODE 0: C fp32, *scale.
// MODE 1: fused-QKV routing, fp16 outputs (q / k / vt transposed), bias=g_b3.
// MODE 2: exp epilogue — C is fp16; writes exp(v*scale)*2^-6.
// MODE 3: row-normalized fp32 — C fp32; multiplies by g_rinv[row].
// ---------------------------------------------------------------------------
template <int MODE>
__global__ void __launch_bounds__(256, 2)
gemm_tc(const __half* __restrict__ A, const __half* __restrict__ B,
        float* __restrict__ C, int K, int ldc, float scale)
{
    constexpr int STAGE = 32768;           // 256 * 128 bytes
    extern __shared__ char dsm[];
    const uint32_t smbase = (smem_u32(dsm) + 127u) & ~127u;

    const int tid  = threadIdx.x;
    const int wid  = tid >> 5;
    const int lane = tid & 31;
    const int g    = lane >> 2;            // 0..7
    const int tig  = lane & 3;             // 0..3
    const int lr   = lane & 7;             // ldsm row within 8x8 matrix
    const int quad = lane >> 3;            // ldsm matrix id 0..3
    const int wm   = (wid & 1) * 64;       // 2 m-warps
    const int wn   = (wid >> 1) * 32;      // 4 n-warps

    const int bm = blockIdx.y * 128;
    const int bn = blockIdx.x * 128;

    // ldsm per-lane row byte-offsets (stage-relative)
    const int hi = quad >> 1;              // k-chunk +1 for matrices 2,3
    uint32_t a_row[4], b_row[2];
    #pragma unroll
    for (int im = 0; im < 4; im++)
        a_row[im] = (uint32_t)((wm + im * 16 + ((quad & 1) << 3) + lr) * 128);
    #pragma unroll
    for (int p = 0; p < 2; p++)
        b_row[p] = (uint32_t)((128 + wn + p * 16 + ((quad & 1) << 3) + lr) * 128);

    // k-step swizzle offsets (kt-invariant)
    uint32_t so_tab[4];
    #pragma unroll
    for (int ks = 0; ks < 4; ks++)
        so_tab[ks] = (uint32_t)(((2 * ks + hi) ^ lr) << 4);

    float c[4][4][4];
    #pragma unroll
    for (int im = 0; im < 4; im++)
        #pragma unroll
        for (int in = 0; in < 4; in++)
            #pragma unroll
            for (int r = 0; r < 4; r++) c[im][in][r] = 0.0f;

    const int KT = K / 64;

    load_stage(smbase + 0 * STAGE, A, B, bm, bn, K, 0, tid);
    asm volatile("cp.async.commit_group;" ::: "memory");
    load_stage(smbase + 1 * STAGE, A, B, bm, bn, K, 1, tid);
    asm volatile("cp.async.commit_group;" ::: "memory");

    for (int kt = 0; kt < KT; kt++) {
        asm volatile("cp.async.wait_group 1;" ::: "memory");
        __syncthreads();   // stage kt%3 visible; prior readers of reused stage done

        const uint32_t sb = smbase + (kt % 3) * STAGE;

        #pragma unroll
        for (int ks = 0; ks < 4; ks++) {
            const uint32_t so = so_tab[ks];
            uint32_t a[4][4], b[2][4];
            #pragma unroll
            for (int im = 0; im < 4; im++) LDSM_X4(a[im], sb + a_row[im] + so);
            #pragma unroll
            for (int p = 0; p < 2; p++)   LDSM_X4(b[p],  sb + b_row[p]  + so);

            // b-frag n-group 2p = {r0, r2}; n-group 2p+1 = {r1, r3}
            #pragma unroll
            for (int im = 0; im < 4; im++)
                #pragma unroll
                for (int p = 0; p < 2; p++) {
                    mma_f16(c[im][2 * p],     a[im], b[p][0], b[p][2]);
                    mma_f16(c[im][2 * p + 1], a[im], b[p][1], b[p][3]);
                }
        }

        // prefetch AFTER compute: keeps LDSM ahead of cp.async in L1tex queue
        if (kt + 2 < KT)
            load_stage(smbase + ((kt + 2) % 3) * STAGE, A, B, bm, bn, K, kt + 2, tid);
        asm volatile("cp.async.commit_group;" ::: "memory");
    }

    // ---- epilogue ----  (col = bn + wn + in*8 + tig*2, row = bm + wm + im*16 + g)
    #pragma unroll
    for (int im = 0; im < 4; im++) {
        #pragma unroll
        for (int in = 0; in < 4; in++) {
            const int row = bm + wm + im * 16 + g;
            const int col = bn + wn + in * 8 + tig * 2;
            float v0 = c[im][in][0], v1 = c[im][in][1];
            float v2 = c[im][in][2], v3 = c[im][in][3];
            if (MODE == 1) {
                float2 b2 = *(const float2*)&g_b3[col];
                v0 += b2.x; v1 += b2.y; v2 += b2.x; v3 += b2.y;
                if (col < DIM) {
                    *(__half2*)&g_q[(size_t)row       * DIM + col] = __floats2half2_rn(v0, v1);
                    *(__half2*)&g_q[(size_t)(row + 8) * DIM + col] = __floats2half2_rn(v2, v3);
                } else if (col < 2 * DIM) {
                    const int cc = col - DIM;
                    *(__half2*)&g_k[(size_t)row       * DIM + cc] = __floats2half2_rn(v0, v1);
                    *(__half2*)&g_k[(size_t)(row + 8) * DIM + cc] = __floats2half2_rn(v2, v3);
                } else {
                    const int cc = col - 2 * DIM;
                    g_vt[(size_t)cc       * NTOK + row    ] = __float2half_rn(v0);
                    g_vt[(size_t)(cc + 1) * NTOK + row    ] = __float2half_rn(v1);
                    g_vt[(size_t)cc       * NTOK + row + 8] = __float2half_rn(v2);
                    g_vt[(size_t)(cc + 1) * NTOK + row + 8] = __float2half_rn(v3);
                }
            } else if (MODE == 2) {
                // E = exp(s) * 2^-6, fp16 (max-free softmax numerator)
                __half* H = (__half*)C;
                float e0 = __expf(v0 * scale) * E_SCALE;
                float e1 = __expf(v1 * scale) * E_SCALE;
                float e2 = __expf(v2 * scale) * E_SCALE;
                float e3 = __expf(v3 * scale) * E_SCALE;
                *(__half2*)&H[(size_t)row       * ldc + col] = __floats2half2_rn(e0, e1);
                *(__half2*)&H[(size_t)(row + 8) * ldc + col] = __floats2half2_rn(e2, e3);
            } else if (MODE == 3) {
                const float r0 = g_rinv[row];
                const float r1 = g_rinv[row + 8];
                *(float2*)&C[(size_t)row       * ldc + col] = make_float2(v0 * r0, v1 * r0);
                *(float2*)&C[(size_t)(row + 8) * ldc + col] = make_float2(v2 * r1, v3 * r1);
            } else {
                v0 *= scale; v1 *= scale; v2 *= scale; v3 *= scale;
                *(float2*)&C[(size_t)row       * ldc + col] = make_float2(v0, v1);
                *(float2*)&C[(size_t)(row + 8) * ldc + col] = make_float2(v2, v3);
            }
        }
    }
}

// ---------------------------------------------------------------------------
// bias concat (own tiny launch)
// ---------------------------------------------------------------------------
__global__ void bias_concat_kernel(const float* __restrict__ bq,
                                   const float* __restrict__ bk,
                                   const float* __restrict__ bv)
{
    int i = blockIdx.x * blockDim.x + threadIdx.x;
    if (i < DIM)            g_b3[i] = bq[i];
    else if (i < 2 * DIM)   g_b3[i] = bk[i - DIM];
    else if (i < 3 * DIM)   g_b3[i] = bv[i - 2 * DIM];
}

// ---------------------------------------------------------------------------
// prep: z=0..2 -> transpose W_z to fp16 into g_wth slab z;
//       z=3    -> feat -> fp16 (g_fth).
// grid (32, 32, 4), block (32, 8).
// ---------------------------------------------------------------------------
__global__ void prep_kernel(const float* __restrict__ feat,
                            const float* __restrict__ Wq,
                            const float* __restrict__ Wk,
                            const float* __restrict__ Wv)
{
    const int z = blockIdx.z;
    if (z < 3) {
        const float* in = (z == 0) ? Wq : (z == 1) ? Wk : Wv;
        __half* out = g_wth + (size_t)z * DIM * DIM;
        __shared__ float t[32][33];
        int bx = blockIdx.x * 32, by = blockIdx.y * 32;
        #pragma unroll
        for (int j = 0; j < 32; j += 8)
            t[threadIdx.y + j][threadIdx.x] =
                in[(size_t)(by + threadIdx.y + j) * DIM + bx + threadIdx.x];
        __syncthreads();
        #pragma unroll
        for (int j = 0; j < 32; j += 8)
            out[(size_t)(bx + threadIdx.y + j) * DIM + by + threadIdx.x] =
                __float2half_rn(t[threadIdx.x][threadIdx.y + j]);
    } else {
        const int bid = blockIdx.y * 32 + blockIdx.x;     // 0..1023
        const int tid = threadIdx.y * 32 + threadIdx.x;   // 0..255
        const float4* fin = (const float4*)feat;
        __half2* fout = (__half2*)g_fth;
        size_t base = (size_t)bid * 2048;
        #pragma unroll
        for (int i = 0; i < 8; i++) {
            size_t idx = base + i * 256 + tid;
            float4 v = fin[idx];
            fout[2 * idx]     = __floats2half2_rn(v.x, v.y);
            fout[2 * idx + 1] = __floats2half2_rn(v.z, v.w);
        }
    }
}

// ---------------------------------------------------------------------------
// rowsum: per-row sum of fp16 E (fp32 accum), store reciprocal.
// One block (256 thr) per row; 8192 half = 1024 uint4 loads.
// ---------------------------------------------------------------------------
__global__ void rowsum_kernel(const __half* __restrict__ E, float* __restrict__ rinv)
{
    const int row = blockIdx.x;
    const int tid = threadIdx.x;
    const uint4* p = (const uint4*)(E + (size_t)row * NTOK);

    float s = 0.0f;
    #pragma unroll
    for (int i = 0; i < 4; i++) {
        uint4 u = p[tid + i * 256];
        float2 f0 = __half22float2(*(const __half2*)&u.x);
        float2 f1 = __half22float2(*(const __half2*)&u.y);
        float2 f2 = __half22float2(*(const __half2*)&u.z);
        float2 f3 = __half22float2(*(const __half2*)&u.w);
        s += (f0.x + f0.y) + (f1.x + f1.y) + (f2.x + f2.y) + (f3.x + f3.y);
    }
    #pragma unroll
    for (int o = 16; o; o >>= 1) s += __shfl_xor_sync(0xffffffffu, s, o);

    __shared__ float red[8];
    if ((tid & 31) == 0) red[tid >> 5] = s;
    __syncthreads();
    if (tid == 0) {
        float t = 0.0f;
        #pragma unroll
        for (int i = 0; i < 8; i++) t += red[i];
        rinv[row] = 1.0f / t;
    }
}

// ---------------------------------------------------------------------------
extern "C" void kernel_launch(void* const* d_in, const int* in_sizes, int n_in,
                              void* d_out, int out_size)
{
    const float* feat = (const float*)d_in[0];
    const float* Wq   = (const float*)d_in[1];
    const float* bq   = (const float*)d_in[2];
    const float* Wk   = (const float*)d_in[3];
    const float* bk   = (const float*)d_in[4];
    const float* Wv   = (const float*)d_in[5];
    const float* bv   = (const float*)d_in[6];
    float* out = (float*)d_out;

    __half *fth, *q, *k, *vt, *e, *wth;
    float *rinv;
    cudaGetSymbolAddress((void**)&fth,  g_fth);
    cudaGetSymbolAddress((void**)&q,    g_q);
    cudaGetSymbolAddress((void**)&k,    g_k);
    cudaGetSymbolAddress((void**)&vt,   g_vt);
    cudaGetSymbolAddress((void**)&e,    g_e);
    cudaGetSymbolAddress((void**)&rinv, g_rinv);
    cudaGetSymbolAddress((void**)&wth,  g_wth);

    const int DSM = 3 * 32768 + 128;
    cudaFuncSetAttribute(gemm_tc<1>, cudaFuncAttributeMaxDynamicSharedMemorySize, DSM);
    cudaFuncSetAttribute(gemm_tc<2>, cudaFuncAttributeMaxDynamicSharedMemorySize, DSM);
    cudaFuncSetAttribute(gemm_tc<3>, cudaFuncAttributeMaxDynamicSharedMemorySize, DSM);

    dim3 gblk(256);                        // GEMM blocks (256 threads)
    dim3 gqkv(3 * DIM / 128, NTOK / 128);  // (24, 64)
    dim3 gsc(NTOK / 128, NTOK / 128);      // (64, 64)
    dim3 gpv(DIM / 128, NTOK / 128);       // (8, 64)

    // launch 0: bias concat
    bias_concat_kernel<<<12, 256>>>(bq, bk, bv);

    // launch 1: prep (W transposes->fp16, feat->fp16)
    prep_kernel<<<dim3(32, 32, 4), dim3(32, 8)>>>(feat, Wq, Wk, Wv);

    // launch 2: fused QKV: [q | k | vt] = fth @ Wcat^T + bcat  (fp16 outputs)
    gemm_tc<1><<<gqkv, gblk, DSM>>>(fth, wth, nullptr, DIM, 0, 1.0f);

    // launch 3: E = exp((q @ k^T)/32) * 2^-6  (fp16, max-free softmax numerator)
    gemm_tc<2><<<gsc, gblk, DSM>>>(q, k, (float*)e, DIM, NTOK, 0.03125f);

    // launch 4: row sums of E -> reciprocals
    rowsum_kernel<<<NTOK, 256>>>(e, rinv);

    // launch 5: out = (E @ vt^T) * rinv[row]   (fp32 output)
    gemm_tc<3><<<gpv, gblk, DSM>>>(e, vt, out, NTOK, DIM, 1.0f);
}

// round 16
// speedup vs baseline: 1.6246x; 1.0904x over previous
#include <cuda_runtime.h>
#include <cuda_fp16.h>
#include <cstdint>

#define NTOK 8192
#define DIM  1024

// ---------------- scratch (allocation-free rule: device globals) -----------
__device__ __half g_fth[(size_t)NTOK * DIM];      // feat as fp16
__device__ __half g_q  [(size_t)NTOK * DIM];      // q fp16
__device__ __half g_k  [(size_t)NTOK * DIM];      // k fp16
__device__ __half g_vt [(size_t)NTOK * DIM];      // v^T fp16: [DIM, NTOK]
__device__ __half g_e  [(size_t)NTOK * NTOK];     // E = exp(s)*2^-6, fp16
__device__ float  g_rinv[NTOK];                   // 1 / rowsum(E)
__device__ __half g_wth[(size_t)3 * DIM * DIM];   // concat W^T fp16
__device__ float  g_b3 [3 * DIM];                 // concat bias fp32

#define E_SCALE 0.015625f                          // 2^-6 overflow guard

// ---------------- helpers --------------------------------------------------
__device__ __forceinline__ uint32_t smem_u32(const void* p) {
    uint32_t a;
    asm("{ .reg .u64 t; cvta.to.shared.u64 t, %1; cvt.u32.u64 %0, t; }" : "=r"(a) : "l"(p));
    return a;
}

#define LDSM_X4(r, addr)                                                       \
    asm volatile("ldmatrix.sync.aligned.m8n8.x4.shared.b16 {%0,%1,%2,%3}, [%4];" \
        : "=r"((r)[0]), "=r"((r)[1]), "=r"((r)[2]), "=r"((r)[3]) : "r"(addr))

__device__ __forceinline__ void mma_f16(float c[4], const uint32_t a[4],
                                        uint32_t b0, uint32_t b1) {
    asm volatile(
        "mma.sync.aligned.m16n8k16.row.col.f32.f16.f16.f32 "
        "{%0,%1,%2,%3}, {%4,%5,%6,%7}, {%8,%9}, {%0,%1,%2,%3};"
        : "+f"(c[0]), "+f"(c[1]), "+f"(c[2]), "+f"(c[3])
        : "r"(a[0]), "r"(a[1]), "r"(a[2]), "r"(a[3]),
          "r"(b0), "r"(b1));
}

#define CP_ASYNC16(dst, src)                                                   \
    asm volatile("cp.async.cg.shared.global [%0], [%1], 16;"                   \
        :: "r"(dst), "l"(src) : "memory")

// ---------------------------------------------------------------------------
// FP16 HMMA NT GEMM: C[M,N] = A[M,K] @ B[N,K]^T  (fp32 accumulate)
// CTA tile 128x128, 256 thr (8 warps of 64x32, 2m x 4n), BK=64 (4 k16 steps),
// 3-stage cp.async pipeline (prefetch AFTER compute — L1tex queue priority),
// 2 CTAs/SM (16 warps/SM = 4/SMSP), single-buffered ldmatrix fragments.
// Loader is strength-reduced: loop-carried gmem pointers (+64 halves per
// k-tile), invariant swizzled smem offset, rotating stage bases (no %3).
// MODE 0: C fp32, *scale.
// MODE 1: fused-QKV routing, fp16 outputs (q / k / vt transposed), bias=g_b3.
// MODE 2: exp epilogue — C is fp16; writes exp(v*scale)*2^-6.
// MODE 3: row-normalized fp32 — C fp32; multiplies by g_rinv[row].
// ---------------------------------------------------------------------------
template <int MODE>
__global__ void __launch_bounds__(256, 2)
gemm_tc(const __half* __restrict__ A, const __half* __restrict__ B,
        float* __restrict__ C, int K, int ldc, float scale)
{
    constexpr int STAGE = 32768;           // 256 * 128 bytes
    extern __shared__ char dsm[];
    const uint32_t smbase = (smem_u32(dsm) + 127u) & ~127u;

    const int tid  = threadIdx.x;
    const int wid  = tid >> 5;
    const int lane = tid & 31;
    const int g    = lane >> 2;            // 0..7
    const int tig  = lane & 3;             // 0..3
    const int lr   = lane & 7;             // ldsm row within 8x8 matrix
    const int quad = lane >> 3;            // ldsm matrix id 0..3
    const int wm   = (wid & 1) * 64;       // 2 m-warps
    const int wn   = (wid >> 1) * 32;      // 4 n-warps

    const int bm = blockIdx.y * 128;
    const int bn = blockIdx.x * 128;

    // ---- strength-reduced loader state ----
    // idx = it*256+tid: ch = tid&7 (inv), row = it*32 + (tid>>3); row&7 = r0&7
    // (inv, since 32 | it*32); A rows for it<4, B rows for it>=4.
    const int r0 = tid >> 3;               // 0..31
    const int ch = tid & 7;                // 0..7
    const __half* pA = A + (size_t)(bm + r0) * K + ch * 8;
    const __half* pB = B + (size_t)(bn + r0) * K + ch * 8;
    const size_t itS = (size_t)32 * K;     // gmem row stride per it (halves)
    const uint32_t dA = (uint32_t)(r0 * 128 + ((ch ^ (r0 & 7)) << 4));

    uint32_t sb_load = smbase;             // rotating stage base (producer)
    uint32_t sb_read = smbase;             // rotating stage base (consumer)

    // ldsm per-lane row byte-offsets (stage-relative)
    const int hi = quad >> 1;              // k-chunk +1 for matrices 2,3
    uint32_t a_row[4], b_row[2];
    #pragma unroll
    for (int im = 0; im < 4; im++)
        a_row[im] = (uint32_t)((wm + im * 16 + ((quad & 1) << 3) + lr) * 128);
    #pragma unroll
    for (int p = 0; p < 2; p++)
        b_row[p] = (uint32_t)((128 + wn + p * 16 + ((quad & 1) << 3) + lr) * 128);

    // k-step swizzle offsets (kt-invariant)
    uint32_t so_tab[4];
    #pragma unroll
    for (int ks = 0; ks < 4; ks++)
        so_tab[ks] = (uint32_t)(((2 * ks + hi) ^ lr) << 4);

    float c[4][4][4];
    #pragma unroll
    for (int im = 0; im < 4; im++)
        #pragma unroll
        for (int in = 0; in < 4; in++)
            #pragma unroll
            for (int r = 0; r < 4; r++) c[im][in][r] = 0.0f;

    const int KT = K / 64;

    // loader: issues 8 cp.async for current k-tile, advances pointers+stage.
    auto do_load = [&]() {
        #pragma unroll
        for (int it = 0; it < 4; it++)
            CP_ASYNC16(sb_load + dA + it * 4096u, pA + it * itS);
        #pragma unroll
        for (int it = 0; it < 4; it++)
            CP_ASYNC16(sb_load + 16384u + dA + it * 4096u, pB + it * itS);
        pA += 64;
        pB += 64;
        sb_load = (sb_load == smbase + 2 * STAGE) ? smbase : sb_load + STAGE;
    };

    do_load();
    asm volatile("cp.async.commit_group;" ::: "memory");
    do_load();
    asm volatile("cp.async.commit_group;" ::: "memory");

    for (int kt = 0; kt < KT; kt++) {
        asm volatile("cp.async.wait_group 1;" ::: "memory");
        __syncthreads();   // stage visible; prior readers of reused stage done

        const uint32_t sb = sb_read;

        #pragma unroll
        for (int ks = 0; ks < 4; ks++) {
            const uint32_t so = so_tab[ks];
            uint32_t a[4][4], b[2][4];
            #pragma unroll
            for (int im = 0; im < 4; im++) LDSM_X4(a[im], sb + a_row[im] + so);
            #pragma unroll
            for (int p = 0; p < 2; p++)   LDSM_X4(b[p],  sb + b_row[p]  + so);

            // b-frag n-group 2p = {r0, r2}; n-group 2p+1 = {r1, r3}
            #pragma unroll
            for (int im = 0; im < 4; im++)
                #pragma unroll
                for (int p = 0; p < 2; p++) {
                    mma_f16(c[im][2 * p],     a[im], b[p][0], b[p][2]);
                    mma_f16(c[im][2 * p + 1], a[im], b[p][1], b[p][3]);
                }
        }

        // prefetch AFTER compute: keeps LDSM ahead of cp.async in L1tex queue
        if (kt + 2 < KT) do_load();
        asm volatile("cp.async.commit_group;" ::: "memory");

        sb_read = (sb_read == smbase + 2 * STAGE) ? smbase : sb_read + STAGE;
    }

    // ---- epilogue ----  (col = bn + wn + in*8 + tig*2, row = bm + wm + im*16 + g)
    #pragma unroll
    for (int im = 0; im < 4; im++) {
        #pragma unroll
        for (int in = 0; in < 4; in++) {
            const int row = bm + wm + im * 16 + g;
            const int col = bn + wn + in * 8 + tig * 2;
            float v0 = c[im][in][0], v1 = c[im][in][1];
            float v2 = c[im][in][2], v3 = c[im][in][3];
            if (MODE == 1) {
                float2 b2 = *(const float2*)&g_b3[col];
                v0 += b2.x; v1 += b2.y; v2 += b2.x; v3 += b2.y;
                if (col < DIM) {
                    *(__half2*)&g_q[(size_t)row       * DIM + col] = __floats2half2_rn(v0, v1);
                    *(__half2*)&g_q[(size_t)(row + 8) * DIM + col] = __floats2half2_rn(v2, v3);
                } else if (col < 2 * DIM) {
                    const int cc = col - DIM;
                    *(__half2*)&g_k[(size_t)row       * DIM + cc] = __floats2half2_rn(v0, v1);
                    *(__half2*)&g_k[(size_t)(row + 8) * DIM + cc] = __floats2half2_rn(v2, v3);
                } else {
                    const int cc = col - 2 * DIM;
                    g_vt[(size_t)cc       * NTOK + row    ] = __float2half_rn(v0);
                    g_vt[(size_t)(cc + 1) * NTOK + row    ] = __float2half_rn(v1);
                    g_vt[(size_t)cc       * NTOK + row + 8] = __float2half_rn(v2);
                    g_vt[(size_t)(cc + 1) * NTOK + row + 8] = __float2half_rn(v3);
                }
            } else if (MODE == 2) {
                // E = exp(s) * 2^-6, fp16 (max-free softmax numerator)
                __half* H = (__half*)C;
                float e0 = __expf(v0 * scale) * E_SCALE;
                float e1 = __expf(v1 * scale) * E_SCALE;
                float e2 = __expf(v2 * scale) * E_SCALE;
                float e3 = __expf(v3 * scale) * E_SCALE;
                *(__half2*)&H[(size_t)row       * ldc + col] = __floats2half2_rn(e0, e1);
                *(__half2*)&H[(size_t)(row + 8) * ldc + col] = __floats2half2_rn(e2, e3);
            } else if (MODE == 3) {
                const float n0 = g_rinv[row];
                const float n1 = g_rinv[row + 8];
                *(float2*)&C[(size_t)row       * ldc + col] = make_float2(v0 * n0, v1 * n0);
                *(float2*)&C[(size_t)(row + 8) * ldc + col] = make_float2(v2 * n1, v3 * n1);
            } else {
                v0 *= scale; v1 *= scale; v2 *= scale; v3 *= scale;
                *(float2*)&C[(size_t)row       * ldc + col] = make_float2(v0, v1);
                *(float2*)&C[(size_t)(row + 8) * ldc + col] = make_float2(v2, v3);
            }
        }
    }
}

// ---------------------------------------------------------------------------
// bias concat (own tiny launch)
// ---------------------------------------------------------------------------
__global__ void bias_concat_kernel(const float* __restrict__ bq,
                                   const float* __restrict__ bk,
                                   const float* __restrict__ bv)
{
    int i = blockIdx.x * blockDim.x + threadIdx.x;
    if (i < DIM)            g_b3[i] = bq[i];
    else if (i < 2 * DIM)   g_b3[i] = bk[i - DIM];
    else if (i < 3 * DIM)   g_b3[i] = bv[i - 2 * DIM];
}

// ---------------------------------------------------------------------------
// prep: z=0..2 -> transpose W_z to fp16 into g_wth slab z;
//       z=3    -> feat -> fp16 (g_fth).
// grid (32, 32, 4), block (32, 8).
// ---------------------------------------------------------------------------
__global__ void prep_kernel(const float* __restrict__ feat,
                            const float* __restrict__ Wq,
                            const float* __restrict__ Wk,
                            const float* __restrict__ Wv)
{
    const int z = blockIdx.z;
    if (z < 3) {
        const float* in = (z == 0) ? Wq : (z == 1) ? Wk : Wv;
        __half* out = g_wth + (size_t)z * DIM * DIM;
        __shared__ float t[32][33];
        int bx = blockIdx.x * 32, by = blockIdx.y * 32;
        #pragma unroll
        for (int j = 0; j < 32; j += 8)
            t[threadIdx.y + j][threadIdx.x] =
                in[(size_t)(by + threadIdx.y + j) * DIM + bx + threadIdx.x];
        __syncthreads();
        #pragma unroll
        for (int j = 0; j < 32; j += 8)
            out[(size_t)(bx + threadIdx.y + j) * DIM + by + threadIdx.x] =
                __float2half_rn(t[threadIdx.x][threadIdx.y + j]);
    } else {
        const int bid = blockIdx.y * 32 + blockIdx.x;     // 0..1023
        const int tid = threadIdx.y * 32 + threadIdx.x;   // 0..255
        const float4* fin = (const float4*)feat;
        __half2* fout = (__half2*)g_fth;
        size_t base = (size_t)bid * 2048;
        #pragma unroll
        for (int i = 0; i < 8; i++) {
            size_t idx = base + i * 256 + tid;
            float4 v = fin[idx];
            fout[2 * idx]     = __floats2half2_rn(v.x, v.y);
            fout[2 * idx + 1] = __floats2half2_rn(v.z, v.w);
        }
    }
}

// ---------------------------------------------------------------------------
// rowsum: per-row sum of fp16 E (fp32 accum), store reciprocal.
// One block (256 thr) per row; 8192 half = 1024 uint4 loads.
// ---------------------------------------------------------------------------
__global__ void rowsum_kernel(const __half* __restrict__ E, float* __restrict__ rinv)
{
    const int row = blockIdx.x;
    const int tid = threadIdx.x;
    const uint4* p = (const uint4*)(E + (size_t)row * NTOK);

    float s = 0.0f;
    #pragma unroll
    for (int i = 0; i < 4; i++) {
        uint4 u = p[tid + i * 256];
        float2 f0 = __half22float2(*(const __half2*)&u.x);
        float2 f1 = __half22float2(*(const __half2*)&u.y);
        float2 f2 = __half22float2(*(const __half2*)&u.z);
        float2 f3 = __half22float2(*(const __half2*)&u.w);
        s += (f0.x + f0.y) + (f1.x + f1.y) + (f2.x + f2.y) + (f3.x + f3.y);
    }
    #pragma unroll
    for (int o = 16; o; o >>= 1) s += __shfl_xor_sync(0xffffffffu, s, o);

    __shared__ float red[8];
    if ((tid & 31) == 0) red[tid >> 5] = s;
    __syncthreads();
    if (tid == 0) {
        float t = 0.0f;
        #pragma unroll
        for (int i = 0; i < 8; i++) t += red[i];
        rinv[row] = 1.0f / t;
    }
}

// ---------------------------------------------------------------------------
extern "C" void kernel_launch(void* const* d_in, const int* in_sizes, int n_in,
                              void* d_out, int out_size)
{
    const float* feat = (const float*)d_in[0];
    const float* Wq   = (const float*)d_in[1];
    const float* bq   = (const float*)d_in[2];
    const float* Wk   = (const float*)d_in[3];
    const float* bk   = (const float*)d_in[4];
    const float* Wv   = (const float*)d_in[5];
    const float* bv   = (const float*)d_in[6];
    float* out = (float*)d_out;

    __half *fth, *q, *k, *vt, *e, *wth;
    float *rinv;
    cudaGetSymbolAddress((void**)&fth,  g_fth);
    cudaGetSymbolAddress((void**)&q,    g_q);
    cudaGetSymbolAddress((void**)&k,    g_k);
    cudaGetSymbolAddress((void**)&vt,   g_vt);
    cudaGetSymbolAddress((void**)&e,    g_e);
    cudaGetSymbolAddress((void**)&rinv, g_rinv);
    cudaGetSymbolAddress((void**)&wth,  g_wth);

    const int DSM = 3 * 32768 + 128;
    cudaFuncSetAttribute(gemm_tc<1>, cudaFuncAttributeMaxDynamicSharedMemorySize, DSM);
    cudaFuncSetAttribute(gemm_tc<2>, cudaFuncAttributeMaxDynamicSharedMemorySize, DSM);
    cudaFuncSetAttribute(gemm_tc<3>, cudaFuncAttributeMaxDynamicSharedMemorySize, DSM);

    dim3 gblk(256);                        // GEMM blocks (256 threads)
    dim3 gqkv(3 * DIM / 128, NTOK / 128);  // (24, 64)
    dim3 gsc(NTOK / 128, NTOK / 128);      // (64, 64)
    dim3 gpv(DIM / 128, NTOK / 128);       // (8, 64)

    // launch 0: bias concat
    bias_concat_kernel<<<12, 256>>>(bq, bk, bv);

    // launch 1: prep (W transposes->fp16, feat->fp16)
    prep_kernel<<<dim3(32, 32, 4), dim3(32, 8)>>>(feat, Wq, Wk, Wv);

    // launch 2: fused QKV: [q | k | vt] = fth @ Wcat^T + bcat  (fp16 outputs)
    gemm_tc<1><<<gqkv, gblk, DSM>>>(fth, wth, nullptr, DIM, 0, 1.0f);

    // launch 3: E = exp((q @ k^T)/32) * 2^-6  (fp16, max-free softmax numerator)
    gemm_tc<2><<<gsc, gblk, DSM>>>(q, k, (float*)e, DIM, NTOK, 0.03125f);

    // launch 4: row sums of E -> reciprocals
    rowsum_kernel<<<NTOK, 256>>>(e, rinv);

    // launch 5: out = (E @ vt^T) * rinv[row]   (fp32 output)
    gemm_tc<3><<<gpv, gblk, DSM>>>(e, vt, out, NTOK, DIM, 1.0f);
}